// round 4
// baseline (speedup 1.0000x reference)
#include <cuda_runtime.h>
#include <cstdint>

#define NN   50000
#define NPAD 50048          // 391 * 128
#define EE   1000000
#define RR   16
#define DD   128
#define GG   64
#define LL   3
#define KTOT 2176           // 16*128 relation cols + 128 root cols
#define NR   (NN * RR)      // 800000
#define SCB  782            // scan blocks: 782*1024 >= NR

// ---------------- static device scratch ----------------
__device__ float g_x[(size_t)NPAD * DD];       // node features (fp32)
__device__ float g_M[(size_t)NPAD * KTOT];     // [n][r*128+d | x] tf32-rounded; pad rows stay 0
__device__ float g_W[KTOT * DD];               // stacked weights [k=r*128+i | root i][o], tf32-rounded
__device__ int   g_cnt[NR];
__device__ int   g_cur[NR];
__device__ int   g_off2[NR + 1];
__device__ int   g_bsum[SCB];
__device__ int   g_bofs[SCB];
__device__ int   g_adj[EE];                    // src, grouped by (dst, rel)
__device__ float g_gcnt[GG];

// ---------------- helpers ----------------
__device__ __forceinline__ float rtf(float f) {       // round-to-nearest tf32, kept as float bits
    unsigned u;
    asm("cvt.rna.tf32.f32 %0, %1;" : "=r"(u) : "f"(f));
    return __uint_as_float(u);
}

__device__ __forceinline__ void mma_tf32(float* c, const unsigned* a, const unsigned* b) {
    asm volatile(
        "mma.sync.aligned.m16n8k8.row.col.f32.tf32.tf32.f32 "
        "{%0,%1,%2,%3}, {%4,%5,%6,%7}, {%8,%9}, {%0,%1,%2,%3};"
        : "+f"(c[0]), "+f"(c[1]), "+f"(c[2]), "+f"(c[3])
        : "r"(a[0]), "r"(a[1]), "r"(a[2]), "r"(a[3]), "r"(b[0]), "r"(b[1]));
}

__device__ __forceinline__ void cp16(float* s, const float* gp) {
    unsigned sa = (unsigned)__cvta_generic_to_shared(s);
    asm volatile("cp.async.cg.shared.global [%0], [%1], 16;" :: "r"(sa), "l"(gp));
}

// ---------------- preprocessing ----------------
__global__ void k_zero() {
    int i = blockIdx.x * 256 + threadIdx.x;
    if (i < NR) { g_cnt[i] = 0; g_cur[i] = 0; }
    if (i < GG) g_gcnt[i] = 0.0f;
}

__global__ void k_count(const int* __restrict__ ei, const int* __restrict__ et) {
    int e = blockIdx.x * 256 + threadIdx.x;
    if (e >= EE) return;
    atomicAdd(&g_cnt[ei[EE + e] * RR + et[e]], 1);
}

__global__ void k_scan1() {       // per-block exclusive scan + block sums
    __shared__ int sh[1024];
    int i = blockIdx.x * 1024 + threadIdx.x;
    int x = (i < NR) ? g_cnt[i] : 0;
    sh[threadIdx.x] = x;
    __syncthreads();
    for (int d = 1; d < 1024; d <<= 1) {
        int t = (threadIdx.x >= d) ? sh[threadIdx.x - d] : 0;
        __syncthreads();
        sh[threadIdx.x] += t;
        __syncthreads();
    }
    if (i < NR) g_off2[i] = sh[threadIdx.x] - x;
    if (threadIdx.x == 1023) g_bsum[blockIdx.x] = sh[1023];
}

__global__ void k_scan2() {       // scan block sums (1 block)
    __shared__ int sh[1024];
    int x = (threadIdx.x < SCB) ? g_bsum[threadIdx.x] : 0;
    sh[threadIdx.x] = x;
    __syncthreads();
    for (int d = 1; d < 1024; d <<= 1) {
        int t = (threadIdx.x >= d) ? sh[threadIdx.x - d] : 0;
        __syncthreads();
        sh[threadIdx.x] += t;
        __syncthreads();
    }
    if (threadIdx.x < SCB) g_bofs[threadIdx.x] = sh[threadIdx.x] - x;
}

__global__ void k_scan3() {
    int i = blockIdx.x * 1024 + threadIdx.x;
    if (i < NR) g_off2[i] += g_bofs[blockIdx.x];
    if (i == 0) g_off2[NR] = EE;
}

__global__ void k_fill(const int* __restrict__ ei, const int* __restrict__ et) {
    int e = blockIdx.x * 256 + threadIdx.x;
    if (e >= EE) return;
    int seg = ei[EE + e] * RR + et[e];
    int p = atomicAdd(&g_cur[seg], 1);
    g_adj[g_off2[seg] + p] = ei[e];
}

__global__ void k_gather(const int* __restrict__ node_ids, const float* __restrict__ emb,
                         const int* __restrict__ batch) {
    int tid = blockIdx.x * 256 + threadIdx.x;
    int n = tid >> 5, l = tid & 31;
    if (n >= NN) return;
    int nid = node_ids[n];
    ((float4*)g_x)[(size_t)n * 32 + l] = ((const float4*)emb)[(size_t)nid * 32 + l];
    if (l == 0) atomicAdd(&g_gcnt[batch[n]], 1.0f);
}

// ---------------- per-layer ----------------
// Stacked weight: g_W[k][o], k = r*128 + i for r<16, else 2048+i for root. tf32-rounded.
__global__ void k_wbuild(const float* __restrict__ comp_l, const float* __restrict__ basis_l,
                         const float* __restrict__ root_l) {
    int idx = blockIdx.x * 256 + threadIdx.x;
    if (idx >= KTOT * DD) return;
    int k = idx >> 7, o = idx & 127;
    float acc;
    if (k < RR * DD) {
        int r = k >> 7, i = k & 127;
        acc = 0.0f;
#pragma unroll
        for (int b = 0; b < 16; b++)
            acc += comp_l[r * 16 + b] * basis_l[((size_t)b * 128 + i) * 128 + o];
    } else {
        acc = root_l[(k - 2048) * 128 + o];
    }
    g_W[idx] = rtf(acc);
}

// Aggregation: warp per dst node; edges sorted by (dst, rel) so each relation is a
// contiguous run -> 4 accumulator regs per lane, no atomics, x reads hit L2 (25MB).
__global__ void __launch_bounds__(256) k_agg() {
    int n = blockIdx.x * 8 + (threadIdx.x >> 5);
    int lane = threadIdx.x & 31;
    if (n >= NN) return;

    int v = 0;
    if (lane < 17) v = g_off2[n * 16 + lane];

    const float4* x4 = (const float4*)g_x;
    float4* M4 = (float4*)g_M;

#pragma unroll
    for (int r = 0; r < 16; r++) {
        int beg = __shfl_sync(0xffffffffu, v, r);
        int end = __shfl_sync(0xffffffffu, v, r + 1);
        float4 a = make_float4(0.f, 0.f, 0.f, 0.f);
        for (int e = beg; e < end; e++) {
            int s = g_adj[e];
            float4 xv = x4[(size_t)s * 32 + lane];
            a.x += xv.x; a.y += xv.y; a.z += xv.z; a.w += xv.w;
        }
        int c = end - beg;
        float ic = 1.0f / (float)(c > 1 ? c : 1);
        float4 o;
        o.x = rtf(a.x * ic); o.y = rtf(a.y * ic); o.z = rtf(a.z * ic); o.w = rtf(a.w * ic);
        M4[(size_t)n * 544 + r * 32 + lane] = o;
    }
    // root operand: append x (tf32-rounded) as cols 2048..2175
    float4 xv = x4[(size_t)n * 32 + lane];
    float4 o;
    o.x = rtf(xv.x); o.y = rtf(xv.y); o.z = rtf(xv.z); o.w = rtf(xv.w);
    M4[(size_t)n * 544 + 512 + lane] = o;
}

// GEMM + fused epilogue: out[128 rows][128] = M'[rows][2176] @ W[2176][128]
// Block 128x128, 8 warps (2x4), warp tile 64x32, K chunks of 32, cp.async double buffer.
#define BK      32
#define KITERS  68
#define ASTR    36
#define BSTR    136
#define SM_FLOATS (2 * 128 * ASTR + 2 * 32 * BSTR)   // 17920 floats = 71680 B

__global__ void __launch_bounds__(256, 2) k_gemm(const float* __restrict__ gam,
                                                 const float* __restrict__ bet,
                                                 const float* __restrict__ bias_l,
                                                 int last, float* __restrict__ out) {
    extern __shared__ float sm[];
    float* As = sm;                    // [2][128][36]
    float* Bs = sm + 2 * 128 * ASTR;   // [2][32][136]
    int tid = threadIdx.x, warp = tid >> 5, lane = tid & 31;
    int wm = warp >> 2, wn = warp & 3;
    int g = lane >> 2, tg = lane & 3;
    size_t mBase = (size_t)blockIdx.x * 128;

    float acc[4][4][4];
#pragma unroll
    for (int mt = 0; mt < 4; mt++)
#pragma unroll
        for (int nt = 0; nt < 4; nt++)
#pragma unroll
            for (int q = 0; q < 4; q++) acc[mt][nt][q] = 0.0f;

    // ---- prefetch chunk 0 ----
    {
        const float* Aa = g_M + mBase * KTOT;
        float* Ab = As;
#pragma unroll
        for (int i = 0; i < 4; i++) {
            int id = tid + i * 256, row = id >> 3, ks = id & 7;
            cp16(Ab + row * ASTR + ks * 4, Aa + (size_t)row * KTOT + ks * 4);
        }
        const float* Ba = g_W;
        float* Bb = Bs;
#pragma unroll
        for (int i = 0; i < 4; i++) {
            int id = tid + i * 256, k = id >> 5, ns = id & 31;
            cp16(Bb + k * BSTR + ns * 4, Ba + k * DD + ns * 4);
        }
        asm volatile("cp.async.commit_group;");
    }

    int buf = 0;
    for (int kc = 0; kc < KITERS; kc++) {
        if (kc + 1 < KITERS) {
            const float* Aa = g_M + mBase * KTOT + (kc + 1) * BK;
            float* Ab = As + (buf ^ 1) * 128 * ASTR;
#pragma unroll
            for (int i = 0; i < 4; i++) {
                int id = tid + i * 256, row = id >> 3, ks = id & 7;
                cp16(Ab + row * ASTR + ks * 4, Aa + (size_t)row * KTOT + ks * 4);
            }
            const float* Ba = g_W + (kc + 1) * BK * DD;
            float* Bb = Bs + (buf ^ 1) * 32 * BSTR;
#pragma unroll
            for (int i = 0; i < 4; i++) {
                int id = tid + i * 256, k = id >> 5, ns = id & 31;
                cp16(Bb + k * BSTR + ns * 4, Ba + k * DD + ns * 4);
            }
            asm volatile("cp.async.commit_group;");
            asm volatile("cp.async.wait_group 1;");
        } else {
            asm volatile("cp.async.wait_group 0;");
        }
        __syncthreads();

        const float* Ab = As + buf * 128 * ASTR;
        const float* Bb = Bs + buf * 32 * BSTR;
#pragma unroll
        for (int kk = 0; kk < 4; kk++) {
            int k0 = kk * 8;
            unsigned a[4][4], b[4][2];
#pragma unroll
            for (int mt = 0; mt < 4; mt++) {
                int r0 = wm * 64 + mt * 16 + g;
                a[mt][0] = __float_as_uint(Ab[r0 * ASTR + k0 + tg]);
                a[mt][1] = __float_as_uint(Ab[(r0 + 8) * ASTR + k0 + tg]);
                a[mt][2] = __float_as_uint(Ab[r0 * ASTR + k0 + tg + 4]);
                a[mt][3] = __float_as_uint(Ab[(r0 + 8) * ASTR + k0 + tg + 4]);
            }
#pragma unroll
            for (int nt = 0; nt < 4; nt++) {
                int nc = wn * 32 + nt * 8 + g;
                b[nt][0] = __float_as_uint(Bb[(k0 + tg) * BSTR + nc]);
                b[nt][1] = __float_as_uint(Bb[(k0 + tg + 4) * BSTR + nc]);
            }
#pragma unroll
            for (int mt = 0; mt < 4; mt++)
#pragma unroll
                for (int nt = 0; nt < 4; nt++)
                    mma_tf32(acc[mt][nt], a[mt], b[nt]);
        }
        __syncthreads();
        buf ^= 1;
    }

    // ---- epilogue: stage C in smem (reuses buffers), per-row LN+relu+residual ----
    float* Cs = sm;   // [128][132]
#pragma unroll
    for (int mt = 0; mt < 4; mt++)
#pragma unroll
        for (int nt = 0; nt < 4; nt++) {
            int r0 = wm * 64 + mt * 16 + g;
            int col = wn * 32 + nt * 8 + tg * 2;
            Cs[r0 * 132 + col]           = acc[mt][nt][0];
            Cs[r0 * 132 + col + 1]       = acc[mt][nt][1];
            Cs[(r0 + 8) * 132 + col]     = acc[mt][nt][2];
            Cs[(r0 + 8) * 132 + col + 1] = acc[mt][nt][3];
        }
    __syncthreads();

    float4 bb = ((const float4*)bias_l)[lane];
    float4 gm = ((const float4*)gam)[lane];
    float4 bt = ((const float4*)bet)[lane];
#pragma unroll
    for (int j = 0; j < 16; j++) {
        int row = warp * 16 + j;
        size_t n = mBase + row;
        if (n >= NN) break;
        float4 v = *(float4*)&Cs[row * 132 + lane * 4];
        v.x += bb.x; v.y += bb.y; v.z += bb.z; v.w += bb.w;
        float s  = v.x + v.y + v.z + v.w;
        float s2 = v.x * v.x + v.y * v.y + v.z * v.z + v.w * v.w;
#pragma unroll
        for (int o = 16; o; o >>= 1) {
            s  += __shfl_xor_sync(0xffffffffu, s, o);
            s2 += __shfl_xor_sync(0xffffffffu, s2, o);
        }
        float mu  = s * (1.0f / 128.0f);
        float var = s2 * (1.0f / 128.0f) - mu * mu;
        float rs  = rsqrtf(var + 1e-5f);
        float4 xi = ((const float4*)g_x)[n * 32 + lane];
        float4 o4;
        o4.x = xi.x + fmaxf((v.x - mu) * rs * gm.x + bt.x, 0.0f);
        o4.y = xi.y + fmaxf((v.y - mu) * rs * gm.y + bt.y, 0.0f);
        o4.z = xi.z + fmaxf((v.z - mu) * rs * gm.z + bt.z, 0.0f);
        o4.w = xi.w + fmaxf((v.w - mu) * rs * gm.w + bt.w, 0.0f);
        float4* dst = last ? (float4*)out : (float4*)g_x;
        dst[n * 32 + lane] = o4;
    }
}

// ---------------- pooling ----------------
__global__ void k_pool(const int* __restrict__ batch, float* __restrict__ out) {
    int tid = blockIdx.x * 256 + threadIdx.x;
    int n = tid >> 5, l = tid & 31;
    if (n >= NN) return;
    int gid = batch[n];
    float4 v = ((const float4*)out)[(size_t)n * 32 + l];
    float* p = out + (size_t)NN * DD + gid * DD + l * 4;
    atomicAdd(p + 0, v.x);
    atomicAdd(p + 1, v.y);
    atomicAdd(p + 2, v.z);
    atomicAdd(p + 3, v.w);
}

__global__ void k_norm(float* __restrict__ out) {
    int i = blockIdx.x * 256 + threadIdx.x;
    if (i >= GG * DD) return;
    float c = g_gcnt[i >> 7];
    out[(size_t)NN * DD + i] *= 1.0f / fmaxf(c, 1.0f);
}

// ---------------- launch ----------------
extern "C" void kernel_launch(void* const* d_in, const int* in_sizes, int n_in,
                              void* d_out, int out_size) {
    const int*   node_ids = (const int*)d_in[0];
    const int*   ei       = (const int*)d_in[1];
    const int*   et       = (const int*)d_in[2];
    const int*   batch    = (const int*)d_in[3];
    const float* emb      = (const float*)d_in[4];
    const float* comp     = (const float*)d_in[5];
    const float* basis    = (const float*)d_in[6];
    const float* root     = (const float*)d_in[7];
    const float* bias     = (const float*)d_in[8];
    const float* gam      = (const float*)d_in[9];
    const float* bet      = (const float*)d_in[10];
    float* out = (float*)d_out;

    cudaFuncSetAttribute(k_gemm, cudaFuncAttributeMaxDynamicSharedMemorySize,
                         SM_FLOATS * 4);

    k_zero<<<(NR + 255) / 256, 256>>>();
    k_count<<<(EE + 255) / 256, 256>>>(ei, et);
    k_scan1<<<SCB, 1024>>>();
    k_scan2<<<1, 1024>>>();
    k_scan3<<<SCB, 1024>>>();
    k_fill<<<(EE + 255) / 256, 256>>>(ei, et);
    k_gather<<<(NN * 32 + 255) / 256, 256>>>(node_ids, emb, batch);

    for (int l = 0; l < LL; l++) {
        k_wbuild<<<(KTOT * DD + 255) / 256, 256>>>(comp + l * RR * 16,
                                                   basis + (size_t)l * 16 * 128 * 128,
                                                   root + (size_t)l * 128 * 128);
        k_agg<<<(NN + 7) / 8, 256>>>();
        k_gemm<<<NPAD / 128, 256, SM_FLOATS * 4>>>(gam + l * 128, bet + l * 128,
                                                   bias + l * 128,
                                                   (l == LL - 1) ? 1 : 0, out);
    }

    cudaMemsetAsync(out + (size_t)NN * DD, 0, (size_t)GG * DD * sizeof(float));
    k_pool<<<(NN * 32 + 255) / 256, 256>>>(batch, out);
    k_norm<<<(GG * DD + 255) / 256, 256>>>(out);
}

// round 5
// speedup vs baseline: 1.0478x; 1.0478x over previous
#include <cuda_runtime.h>
#include <cstdint>

#define NN   50000
#define NPAD 50048          // 391 * 128
#define EE   1000000
#define RR   16
#define DD   128
#define GG   64
#define LL   3
#define NR   (NN * RR)          // 800000
#define NRP  (NPAD * RR)        // 800768 = 782*1024 exactly
#define SCB  782
#define KCH  68                 // 17 relations * 4 sub-chunks of K=32

// ---------------- static device scratch ----------------
__device__ float g_xa[(size_t)NPAD * DD];
__device__ float g_xb[(size_t)NPAD * DD];
__device__ float g_W[(RR + 1) * DD * DD];     // stacked [k = r*128+i | root i][o], tf32-rounded
__device__ int   g_cnt[NR];
__device__ int   g_cur[NR];
__device__ int   g_off2[NRP + 1];
__device__ int   g_bsum[SCB];
__device__ int   g_bofs[SCB];
__device__ int   g_adj[EE];                   // src, grouped by (dst, rel)
__device__ float g_gcnt[GG];

// ---------------- helpers ----------------
__device__ __forceinline__ float rtf(float f) {
    unsigned u;
    asm("cvt.rna.tf32.f32 %0, %1;" : "=r"(u) : "f"(f));
    return __uint_as_float(u);
}

__device__ __forceinline__ void mma_tf32(float* c, const unsigned* a, const unsigned* b) {
    asm volatile(
        "mma.sync.aligned.m16n8k8.row.col.f32.tf32.tf32.f32 "
        "{%0,%1,%2,%3}, {%4,%5,%6,%7}, {%8,%9}, {%0,%1,%2,%3};"
        : "+f"(c[0]), "+f"(c[1]), "+f"(c[2]), "+f"(c[3])
        : "r"(a[0]), "r"(a[1]), "r"(a[2]), "r"(a[3]), "r"(b[0]), "r"(b[1]));
}

__device__ __forceinline__ void cp16(float* s, const float* gp) {
    unsigned sa = (unsigned)__cvta_generic_to_shared(s);
    asm volatile("cp.async.cg.shared.global [%0], [%1], 16;" :: "r"(sa), "l"(gp));
}

// ---------------- preprocessing ----------------
__global__ void k_zero() {
    int i = blockIdx.x * 256 + threadIdx.x;
    if (i < NR) { g_cnt[i] = 0; g_cur[i] = 0; }
    if (i < GG) g_gcnt[i] = 0.0f;
}

__global__ void k_count(const int* __restrict__ ei, const int* __restrict__ et) {
    int e = blockIdx.x * 256 + threadIdx.x;
    if (e >= EE) return;
    atomicAdd(&g_cnt[ei[EE + e] * RR + et[e]], 1);
}

__global__ void k_scan1() {       // per-block exclusive scan over NRP entries
    __shared__ int sh[1024];
    int i = blockIdx.x * 1024 + threadIdx.x;
    int x = (i < NR) ? g_cnt[i] : 0;
    sh[threadIdx.x] = x;
    __syncthreads();
    for (int d = 1; d < 1024; d <<= 1) {
        int t = (threadIdx.x >= d) ? sh[threadIdx.x - d] : 0;
        __syncthreads();
        sh[threadIdx.x] += t;
        __syncthreads();
    }
    g_off2[i] = sh[threadIdx.x] - x;
    if (threadIdx.x == 1023) g_bsum[blockIdx.x] = sh[1023];
}

__global__ void k_scan2() {
    __shared__ int sh[1024];
    int x = (threadIdx.x < SCB) ? g_bsum[threadIdx.x] : 0;
    sh[threadIdx.x] = x;
    __syncthreads();
    for (int d = 1; d < 1024; d <<= 1) {
        int t = (threadIdx.x >= d) ? sh[threadIdx.x - d] : 0;
        __syncthreads();
        sh[threadIdx.x] += t;
        __syncthreads();
    }
    if (threadIdx.x < SCB) g_bofs[threadIdx.x] = sh[threadIdx.x] - x;
}

__global__ void k_scan3() {
    int i = blockIdx.x * 1024 + threadIdx.x;
    g_off2[i] += g_bofs[blockIdx.x];
    if (i == 0) g_off2[NRP] = EE;
}

__global__ void k_fill(const int* __restrict__ ei, const int* __restrict__ et) {
    int e = blockIdx.x * 256 + threadIdx.x;
    if (e >= EE) return;
    int seg = ei[EE + e] * RR + et[e];
    int p = atomicAdd(&g_cur[seg], 1);
    g_adj[g_off2[seg] + p] = ei[e];
}

__global__ void k_gather(const int* __restrict__ node_ids, const float* __restrict__ emb,
                         const int* __restrict__ batch) {
    int tid = blockIdx.x * 256 + threadIdx.x;
    int n = tid >> 5, l = tid & 31;
    if (n >= NN) return;
    int nid = node_ids[n];
    ((float4*)g_xa)[(size_t)n * 32 + l] = ((const float4*)emb)[(size_t)nid * 32 + l];
    if (l == 0) atomicAdd(&g_gcnt[batch[n]], 1.0f);
}

// ---------------- per-layer weight build (tf32-rounded) ----------------
__global__ void k_wbuild(const float* __restrict__ comp_l, const float* __restrict__ basis_l,
                         const float* __restrict__ root_l) {
    int idx = blockIdx.x * 256 + threadIdx.x;
    if (idx >= (RR + 1) * DD * DD) return;
    int k = idx >> 7, o = idx & 127;
    float acc;
    if (k < RR * DD) {
        int r = k >> 7, i = k & 127;
        acc = 0.0f;
#pragma unroll
        for (int b = 0; b < 16; b++)
            acc += comp_l[r * 16 + b] * basis_l[((size_t)b * 128 + i) * 128 + o];
    } else {
        acc = root_l[(k - 2048) * 128 + o];
    }
    g_W[idx] = rtf(acc);
}

// ---------------- fused layer kernel ----------------
// Block = 128 dst nodes. For r = 0..16 (16 = root/identity):
//   aggregate relation-r means into As[128][132] (x reads hit L2),
//   then C += As @ W_r via tf32 mma, W streamed in 32-k sub-chunks (cp.async dbuf).
// Epilogue: bias + layernorm + relu + residual, written to xout.
#define ASTR 132
#define BSTR 136
#define SM_BYTES ((128 * ASTR + 2 * 32 * BSTR + 2052) * 4)   // 110608 B

__global__ void __launch_bounds__(256, 2) k_fused(const float* __restrict__ xin,
                                                  float* __restrict__ xout,
                                                  const float* __restrict__ gam,
                                                  const float* __restrict__ bet,
                                                  const float* __restrict__ bias_l) {
    extern __shared__ float sm[];
    float* As = sm;                         // [128][132]
    float* Bs = sm + 128 * ASTR;            // [2][32][136]
    int*   offs = (int*)(sm + 128 * ASTR + 2 * 32 * BSTR);  // [2049]
    int tid = threadIdx.x, warp = tid >> 5, lane = tid & 31;
    int wm = warp >> 2, wn = warp & 3;
    int g = lane >> 2, tg = lane & 3;
    size_t mBase = (size_t)blockIdx.x * 128;

    for (int i = tid; i < 2049; i += 256) offs[i] = g_off2[mBase * 16 + i];

    // prefetch W chunk 0
    {
        const float* Ba = g_W;
#pragma unroll
        for (int i = 0; i < 4; i++) {
            int id = tid + i * 256, k = id >> 5, ns = id & 31;
            cp16(Bs + k * BSTR + ns * 4, Ba + k * DD + ns * 4);
        }
        asm volatile("cp.async.commit_group;");
    }
    __syncthreads();   // offs ready

    float acc[4][4][4];
#pragma unroll
    for (int mt = 0; mt < 4; mt++)
#pragma unroll
        for (int nt = 0; nt < 4; nt++)
#pragma unroll
            for (int q = 0; q < 4; q++) acc[mt][nt][q] = 0.0f;

    const float4* x4 = (const float4*)xin;
    int buf = 0;

    for (int r = 0; r < 17; r++) {
        // ---- aggregate relation r into As (warp owns 16 rows) ----
        if (r < 16) {
#pragma unroll 1
            for (int j = 0; j < 16; j++) {
                int nl = warp * 16 + j;
                int beg = offs[nl * 16 + r];
                int end = offs[nl * 16 + r + 1];
                float4 a = make_float4(0.f, 0.f, 0.f, 0.f);
                for (int e = beg; e < end; e++) {
                    int s = g_adj[e];
                    float4 xv = x4[(size_t)s * 32 + lane];
                    a.x += xv.x; a.y += xv.y; a.z += xv.z; a.w += xv.w;
                }
                int c = end - beg;
                float ic = 1.0f / (float)(c > 1 ? c : 1);
                *(float4*)&As[nl * ASTR + lane * 4] =
                    make_float4(rtf(a.x * ic), rtf(a.y * ic), rtf(a.z * ic), rtf(a.w * ic));
            }
        } else {
#pragma unroll 1
            for (int j = 0; j < 16; j++) {
                int nl = warp * 16 + j;
                size_t n = mBase + nl;
                float4 xv = (n < NN) ? x4[n * 32 + lane] : make_float4(0.f, 0.f, 0.f, 0.f);
                *(float4*)&As[nl * ASTR + lane * 4] =
                    make_float4(rtf(xv.x), rtf(xv.y), rtf(xv.z), rtf(xv.w));
            }
        }
        __syncthreads();   // As ready

#pragma unroll 1
        for (int sc = 0; sc < 4; sc++) {
            int kb = r * 4 + sc;
            if (kb + 1 < KCH) {
                const float* Ba = g_W + (size_t)(kb + 1) * 32 * DD;
                float* Bb = Bs + (buf ^ 1) * 32 * BSTR;
#pragma unroll
                for (int i = 0; i < 4; i++) {
                    int id = tid + i * 256, k = id >> 5, ns = id & 31;
                    cp16(Bb + k * BSTR + ns * 4, Ba + k * DD + ns * 4);
                }
                asm volatile("cp.async.commit_group;");
                asm volatile("cp.async.wait_group 1;");
            } else {
                asm volatile("cp.async.wait_group 0;");
            }
            __syncthreads();   // Bs[buf] valid for everyone

            const float* Bb = Bs + buf * 32 * BSTR;
#pragma unroll
            for (int kk = 0; kk < 4; kk++) {
                int k0 = sc * 32 + kk * 8;   // col within As
                int bk = kk * 8;             // row within Bs
                unsigned a[4][4], b[4][2];
#pragma unroll
                for (int mt = 0; mt < 4; mt++) {
                    int r0 = wm * 64 + mt * 16 + g;
                    a[mt][0] = __float_as_uint(As[r0 * ASTR + k0 + tg]);
                    a[mt][1] = __float_as_uint(As[(r0 + 8) * ASTR + k0 + tg]);
                    a[mt][2] = __float_as_uint(As[r0 * ASTR + k0 + tg + 4]);
                    a[mt][3] = __float_as_uint(As[(r0 + 8) * ASTR + k0 + tg + 4]);
                }
#pragma unroll
                for (int nt = 0; nt < 4; nt++) {
                    int nc = wn * 32 + nt * 8 + g;
                    b[nt][0] = __float_as_uint(Bb[(bk + tg) * BSTR + nc]);
                    b[nt][1] = __float_as_uint(Bb[(bk + tg + 4) * BSTR + nc]);
                }
#pragma unroll
                for (int mt = 0; mt < 4; mt++)
#pragma unroll
                    for (int nt = 0; nt < 4; nt++)
                        mma_tf32(acc[mt][nt], a[mt], b[nt]);
            }
            buf ^= 1;
            __syncthreads();   // done reading old Bs buf / As before reuse
        }
    }

    // ---- epilogue: stage C in smem, per-row LN + relu + residual ----
    float* Cs = sm;   // reuses As region [128][132]
#pragma unroll
    for (int mt = 0; mt < 4; mt++)
#pragma unroll
        for (int nt = 0; nt < 4; nt++) {
            int r0 = wm * 64 + mt * 16 + g;
            int col = wn * 32 + nt * 8 + tg * 2;
            Cs[r0 * ASTR + col]           = acc[mt][nt][0];
            Cs[r0 * ASTR + col + 1]       = acc[mt][nt][1];
            Cs[(r0 + 8) * ASTR + col]     = acc[mt][nt][2];
            Cs[(r0 + 8) * ASTR + col + 1] = acc[mt][nt][3];
        }
    __syncthreads();

    float4 bb = ((const float4*)bias_l)[lane];
    float4 gm = ((const float4*)gam)[lane];
    float4 bt = ((const float4*)bet)[lane];
#pragma unroll 1
    for (int j = 0; j < 16; j++) {
        int row = warp * 16 + j;
        size_t n = mBase + row;
        if (n >= NN) break;
        float4 v = *(float4*)&Cs[row * ASTR + lane * 4];
        v.x += bb.x; v.y += bb.y; v.z += bb.z; v.w += bb.w;
        float s  = v.x + v.y + v.z + v.w;
        float s2 = v.x * v.x + v.y * v.y + v.z * v.z + v.w * v.w;
#pragma unroll
        for (int o = 16; o; o >>= 1) {
            s  += __shfl_xor_sync(0xffffffffu, s, o);
            s2 += __shfl_xor_sync(0xffffffffu, s2, o);
        }
        float mu  = s * (1.0f / 128.0f);
        float var = s2 * (1.0f / 128.0f) - mu * mu;
        float rs  = rsqrtf(var + 1e-5f);
        float4 xi = x4[n * 32 + lane];
        float4 o4;
        o4.x = xi.x + fmaxf((v.x - mu) * rs * gm.x + bt.x, 0.0f);
        o4.y = xi.y + fmaxf((v.y - mu) * rs * gm.y + bt.y, 0.0f);
        o4.z = xi.z + fmaxf((v.z - mu) * rs * gm.z + bt.z, 0.0f);
        o4.w = xi.w + fmaxf((v.w - mu) * rs * gm.w + bt.w, 0.0f);
        ((float4*)xout)[n * 32 + lane] = o4;
    }
}

// ---------------- pooling ----------------
__global__ void k_pool(const int* __restrict__ batch, float* __restrict__ out) {
    int tid = blockIdx.x * 256 + threadIdx.x;
    int n = tid >> 5, l = tid & 31;
    if (n >= NN) return;
    int gid = batch[n];
    float4 v = ((const float4*)out)[(size_t)n * 32 + l];
    float* p = out + (size_t)NN * DD + gid * DD + l * 4;
    atomicAdd(p + 0, v.x);
    atomicAdd(p + 1, v.y);
    atomicAdd(p + 2, v.z);
    atomicAdd(p + 3, v.w);
}

__global__ void k_norm(float* __restrict__ out) {
    int i = blockIdx.x * 256 + threadIdx.x;
    if (i >= GG * DD) return;
    float c = g_gcnt[i >> 7];
    out[(size_t)NN * DD + i] *= 1.0f / fmaxf(c, 1.0f);
}

// ---------------- launch ----------------
extern "C" void kernel_launch(void* const* d_in, const int* in_sizes, int n_in,
                              void* d_out, int out_size) {
    const int*   node_ids = (const int*)d_in[0];
    const int*   ei       = (const int*)d_in[1];
    const int*   et       = (const int*)d_in[2];
    const int*   batch    = (const int*)d_in[3];
    const float* emb      = (const float*)d_in[4];
    const float* comp     = (const float*)d_in[5];
    const float* basis    = (const float*)d_in[6];
    const float* root     = (const float*)d_in[7];
    const float* bias     = (const float*)d_in[8];
    const float* gam      = (const float*)d_in[9];
    const float* bet      = (const float*)d_in[10];
    float* out = (float*)d_out;

    cudaFuncSetAttribute(k_fused, cudaFuncAttributeMaxDynamicSharedMemorySize, SM_BYTES);

    k_zero<<<(NR + 255) / 256, 256>>>();
    k_count<<<(EE + 255) / 256, 256>>>(ei, et);
    k_scan1<<<SCB, 1024>>>();
    k_scan2<<<1, 1024>>>();
    k_scan3<<<SCB, 1024>>>();
    k_fill<<<(EE + 255) / 256, 256>>>(ei, et);
    k_gather<<<(NN * 32 + 255) / 256, 256>>>(node_ids, emb, batch);

    float *xa, *xb;
    cudaGetSymbolAddress((void**)&xa, g_xa);
    cudaGetSymbolAddress((void**)&xb, g_xb);
    const float* src3[3] = {xa, xb, xa};
    float*       dst3[3] = {xb, xa, out};

    for (int l = 0; l < LL; l++) {
        k_wbuild<<<((RR + 1) * DD * DD + 255) / 256, 256>>>(
            comp + l * RR * 16,
            basis + (size_t)l * 16 * 128 * 128,
            root + (size_t)l * 128 * 128);
        k_fused<<<NPAD / 128, 256, SM_BYTES>>>(src3[l], dst3[l],
                                               gam + l * 128, bet + l * 128,
                                               bias + l * 128);
    }

    cudaMemsetAsync(out + (size_t)NN * DD, 0, (size_t)GG * DD * sizeof(float));
    k_pool<<<(NN * 32 + 255) / 256, 256>>>(batch, out);
    k_norm<<<(GG * DD + 255) / 256, 256>>>(out);
}